// round 9
// baseline (speedup 1.0000x reference)
#include <cuda_runtime.h>
#include <cuda_fp16.h>

#define N_NODES 100000
#define N_EDGES 1600000
#define F 64
#define NTILES ((N_NODES + 1023) / 1024)   // 98

typedef unsigned long long ull;

// ---------------- scratch (static device globals; no allocation) ----------------
__device__ int    g_deg[N_NODES];
__device__ int    g_cursor[N_NODES];
__device__ int    g_row_ptr[N_NODES + 1];
__device__ int    g_csr_src[N_EDGES];
__device__ int    g_tile_sum[NTILES];
__device__ int    g_tile_off[NTILES];
__device__ float  g_mean[(size_t)N_NODES * F];
__device__ float  g_h1[(size_t)N_NODES * F];
__device__ __half g_xh[(size_t)N_NODES * F];   // fp16 copy of current agg input
__device__ float  g_sa[N_NODES];
__device__ float  g_sb[N_NODES];

// ---------------- packed f32x2 helpers (Blackwell FFMA2) ----------------
__device__ __forceinline__ ull fma2(ull a, ull b, ull c) {
    ull d;
    asm("fma.rn.f32x2 %0, %1, %2, %3;" : "=l"(d) : "l"(a), "l"(b), "l"(c));
    return d;
}
__device__ __forceinline__ ull pack2(float x, float y) {
    ull r; asm("mov.b64 %0, {%1, %2};" : "=l"(r) : "f"(x), "f"(y)); return r;
}
__device__ __forceinline__ float hsum2(ull a) {
    float x, y; asm("mov.b64 {%0, %1}, %2;" : "=f"(x), "=f"(y) : "l"(a)); return x + y;
}

// ---------------- CSR build ----------------
__global__ void hist_kernel(const int* __restrict__ ei) {
    int e4 = blockIdx.x * blockDim.x + threadIdx.x;
    if (e4 >= N_EDGES / 4) return;
    int4 d = __ldg((const int4*)(ei + N_EDGES) + e4);
    atomicAdd(&g_deg[d.x], 1);
    atomicAdd(&g_deg[d.y], 1);
    atomicAdd(&g_deg[d.z], 1);
    atomicAdd(&g_deg[d.w], 1);
}

__global__ void scanA_kernel() {
    __shared__ int wsum[32];
    int t = threadIdx.x, b = blockIdx.x;
    int i = b * 1024 + t;
    int v = (i < N_NODES) ? g_deg[i] : 0;
#pragma unroll
    for (int off = 16; off; off >>= 1)
        v += __shfl_down_sync(0xFFFFFFFFu, v, off);
    if ((t & 31) == 0) wsum[t >> 5] = v;
    __syncthreads();
    if (t < 32) {
        int s = wsum[t];
#pragma unroll
        for (int off = 16; off; off >>= 1)
            s += __shfl_down_sync(0xFFFFFFFFu, s, off);
        if (t == 0) g_tile_sum[b] = s;
    }
}

__global__ void scanB_kernel() {
    __shared__ int sh[NTILES];
    int t = threadIdx.x;
    if (t < NTILES) sh[t] = g_tile_sum[t];
    __syncthreads();
    if (t == 0) {
        int run = 0;
        for (int i = 0; i < NTILES; i++) { int v = sh[i]; sh[i] = run; run += v; }
        g_row_ptr[N_NODES] = run;
    }
    __syncthreads();
    if (t < NTILES) g_tile_off[t] = sh[t];
}

__global__ void scanC_kernel() {
    __shared__ int wsum[32];
    int t = threadIdx.x, b = blockIdx.x;
    int i = b * 1024 + t;
    int v = (i < N_NODES) ? g_deg[i] : 0;
    int lane = t & 31, w = t >> 5;
    int x = v;
#pragma unroll
    for (int off = 1; off < 32; off <<= 1) {
        int y = __shfl_up_sync(0xFFFFFFFFu, x, off);
        if (lane >= off) x += y;
    }
    if (lane == 31) wsum[w] = x;
    __syncthreads();
    if (t < 32) {
        int s = wsum[t];
#pragma unroll
        for (int off = 1; off < 32; off <<= 1) {
            int y = __shfl_up_sync(0xFFFFFFFFu, s, off);
            if (t >= off) s += y;
        }
        wsum[t] = s;
    }
    __syncthreads();
    int base = g_tile_off[b] + (w ? wsum[w - 1] : 0);
    int excl = base + x - v;
    if (i < N_NODES) { g_row_ptr[i] = excl; g_cursor[i] = excl; }
}

__global__ void fill_kernel(const int* __restrict__ ei) {
    int e4 = blockIdx.x * blockDim.x + threadIdx.x;
    if (e4 >= N_EDGES / 4) return;
    int4 s = __ldg((const int4*)ei + e4);
    int4 d = __ldg((const int4*)(ei + N_EDGES) + e4);
    g_csr_src[atomicAdd(&g_cursor[d.x], 1)] = s.x;
    g_csr_src[atomicAdd(&g_cursor[d.y], 1)] = s.y;
    g_csr_src[atomicAdd(&g_cursor[d.z], 1)] = s.z;
    g_csr_src[atomicAdd(&g_cursor[d.w], 1)] = s.w;
}

// ---------------- fp32 -> fp16 conversion of x ----------------
__global__ void conv_kernel(const float* __restrict__ x) {
    int i = blockIdx.x * blockDim.x + threadIdx.x;   // over N*F/4
    if (i >= N_NODES * F / 4) return;
    float4 v = __ldg((const float4*)x + i);
    __half2 a = __floats2half2_rn(v.x, v.y);
    __half2 b = __floats2half2_rn(v.z, v.w);
    uint2 o;
    o.x = *(unsigned*)&a;
    o.y = *(unsigned*)&b;
    ((uint2*)g_xh)[i] = o;
}

// ---------------- mean aggregation (fp16 gather, fp32 accumulate) ----------------
// Warp-per-node, 32 lanes x half2 (one LDG.32 warp-instr = 128B row per edge).
__global__ void agg_kernel() {
    int warp = (blockIdx.x * blockDim.x + threadIdx.x) >> 5;
    int lane = threadIdx.x & 31;
    if (warp >= N_NODES) return;

    const int beg = g_row_ptr[warp];
    const int end = g_row_ptr[warp + 1];

    const __half2* __restrict__ x2 = (const __half2*)g_xh;

    float2 a0 = make_float2(0.f, 0.f);
    float2 a1 = make_float2(0.f, 0.f);
    float2 a2 = make_float2(0.f, 0.f);
    float2 a3 = make_float2(0.f, 0.f);

    for (int base = beg; base < end; base += 8) {
        int s[8];
#pragma unroll
        for (int u = 0; u < 8; u++)
            s[u] = (base + u < end) ? __ldg(g_csr_src + base + u) : -1;

        float2 v[8];
#pragma unroll
        for (int u = 0; u < 8; u++)
            v[u] = (s[u] >= 0) ? __half22float2(__ldg(x2 + (size_t)s[u] * 32 + lane))
                               : make_float2(0.f, 0.f);

        a0.x += v[0].x + v[4].x; a0.y += v[0].y + v[4].y;
        a1.x += v[1].x + v[5].x; a1.y += v[1].y + v[5].y;
        a2.x += v[2].x + v[6].x; a2.y += v[2].y + v[6].y;
        a3.x += v[3].x + v[7].x; a3.y += v[3].y + v[7].y;
    }

    float2 acc;
    acc.x = (a0.x + a1.x) + (a2.x + a3.x);
    acc.y = (a0.y + a1.y) + (a2.y + a3.y);
    float inv = (end > beg) ? 1.0f / (float)(end - beg) : 0.0f;
    acc.x *= inv; acc.y *= inv;
    ((float2*)g_mean)[(size_t)warp * 32 + lane] = acc;
}

// ---------------- SAGE transform ----------------
// LAYER 0: h1 = relu(mean@Wl^T + b + x@Wr^T), stored fp32 + fp16 (for agg2).
// LAYER 1: h2 computed in registers only; sa/sb = h2 . Wlin halves, reduced by
//          warp shfl + 2 atomicAdds per warp. No barriers in the loop.
template<int LAYER>
__global__ void __launch_bounds__(256, 1) transform_kernel(
    const float* __restrict__ xin,
    const float* __restrict__ Wl, const float* __restrict__ bl,
    const float* __restrict__ Wr, const float* __restrict__ Wlin,
    float* __restrict__ hout, __half* __restrict__ houth)
{
    const int j = threadIdx.x & 63;
    const int g = threadIdx.x >> 6;
    const int lane = threadIdx.x & 31;

    ull wl[32], wr[32];
#pragma unroll
    for (int k = 0; k < 16; k++) {
        float4 a = __ldg((const float4*)Wl + j * 16 + k);
        float4 b = __ldg((const float4*)Wr + j * 16 + k);
        wl[2 * k]     = pack2(a.x, a.y);
        wl[2 * k + 1] = pack2(a.z, a.w);
        wr[2 * k]     = pack2(b.x, b.y);
        wr[2 * k + 1] = pack2(b.z, b.w);
    }
    const float bias = __ldg(bl + j);
    float wa = 0.f, wb = 0.f;
    if (LAYER == 1) { wa = __ldg(Wlin + j); wb = __ldg(Wlin + 64 + j); }

    const ulonglong2* __restrict__ m2b = (const ulonglong2*)g_mean;
    const ulonglong2* __restrict__ x2b = (const ulonglong2*)xin;

    for (int n = blockIdx.x * 4 + g; n < N_NODES; n += gridDim.x * 4) {
        const ulonglong2* m2 = m2b + (size_t)n * 16;
        const ulonglong2* x2 = x2b + (size_t)n * 16;
        ull a0 = 0, a1 = 0, a2 = 0, a3 = 0;
#pragma unroll
        for (int k = 0; k < 16; k++) {
            ulonglong2 mv = __ldg(m2 + k);
            ulonglong2 xv = __ldg(x2 + k);
            a0 = fma2(wl[2 * k],     mv.x, a0);
            a1 = fma2(wl[2 * k + 1], mv.y, a1);
            a2 = fma2(wr[2 * k],     xv.x, a2);
            a3 = fma2(wr[2 * k + 1], xv.y, a3);
        }
        float s = fmaxf(hsum2(a0) + hsum2(a1) + hsum2(a2) + hsum2(a3) + bias, 0.0f);

        if (LAYER == 0) {
            hout[(size_t)n * 64 + j]  = s;
            houth[(size_t)n * 64 + j] = __float2half_rn(s);
        } else {
            float pa = s * wa, pb = s * wb;
#pragma unroll
            for (int off = 16; off; off >>= 1) {
                pa += __shfl_down_sync(0xFFFFFFFFu, pa, off);
                pb += __shfl_down_sync(0xFFFFFFFFu, pb, off);
            }
            if (lane == 0) {
                atomicAdd(&g_sa[n], pa);
                atomicAdd(&g_sb[n], pb);
            }
        }
    }
}

// ---------------- final edge scores (4 edges per thread) ----------------
__global__ void edge_kernel(const int* __restrict__ ei,
                            const float* __restrict__ blin,
                            float* __restrict__ out)
{
    int e4 = blockIdx.x * blockDim.x + threadIdx.x;
    if (e4 >= N_EDGES / 4) return;
    int4 s = __ldg((const int4*)ei + e4);
    int4 d = __ldg((const int4*)(ei + N_EDGES) + e4);
    float b = __ldg(blin);
    float4 r;
    r.x = g_sa[s.x] + g_sb[d.x] + b;
    r.y = g_sa[s.y] + g_sb[d.y] + b;
    r.z = g_sa[s.z] + g_sb[d.z] + b;
    r.w = g_sa[s.w] + g_sb[d.w] + b;
    ((float4*)out)[e4] = r;
}

// ---------------- launch ----------------
extern "C" void kernel_launch(void* const* d_in, const int* in_sizes, int n_in,
                              void* d_out, int out_size)
{
    const float* x    = (const float*)d_in[0];
    const int*   ei   = (const int*)  d_in[1];
    const float* W1l  = (const float*)d_in[2];
    const float* b1l  = (const float*)d_in[3];
    const float* W1r  = (const float*)d_in[4];
    const float* W2l  = (const float*)d_in[5];
    const float* b2l  = (const float*)d_in[6];
    const float* W2r  = (const float*)d_in[7];
    const float* Wlin = (const float*)d_in[8];
    const float* blin = (const float*)d_in[9];
    float* out = (float*)d_out;

    const int E4B = (N_EDGES / 4 + 255) / 256;

    float*  p_h1;  cudaGetSymbolAddress((void**)&p_h1,  g_h1);
    __half* p_xh;  cudaGetSymbolAddress((void**)&p_xh,  g_xh);
    int*    p_deg; cudaGetSymbolAddress((void**)&p_deg, g_deg);
    float*  p_sa;  cudaGetSymbolAddress((void**)&p_sa,  g_sa);
    float*  p_sb;  cudaGetSymbolAddress((void**)&p_sb,  g_sb);

    // memset nodes (not kernel launches)
    cudaMemsetAsync(p_deg, 0, N_NODES * sizeof(int), 0);
    cudaMemsetAsync(p_sa,  0, N_NODES * sizeof(float), 0);
    cudaMemsetAsync(p_sb,  0, N_NODES * sizeof(float), 0);

    hist_kernel<<<E4B, 256>>>(ei);
    scanA_kernel<<<NTILES, 1024>>>();
    scanB_kernel<<<1, 128>>>();
    scanC_kernel<<<NTILES, 1024>>>();
    conv_kernel<<<(N_NODES * F / 4 + 255) / 256, 256>>>(x);
    fill_kernel<<<E4B, 256>>>(ei);

    // layer 1: agg on fp16 x; transform writes fp32 h1 + fp16 copy into g_xh
    agg_kernel<<<N_NODES * 32 / 256, 256>>>();
    transform_kernel<0><<<152, 256>>>(x, W1l, b1l, W1r, Wlin, p_h1, p_xh);

    // layer 2: agg on fp16 h1; transform fuses edge-scorer halves via atomics
    agg_kernel<<<N_NODES * 32 / 256, 256>>>();
    transform_kernel<1><<<152, 256>>>(p_h1, W2l, b2l, W2r, Wlin, nullptr, nullptr);

    // edge scoring
    edge_kernel<<<E4B, 256>>>(ei, blin, out);
}

// round 10
// speedup vs baseline: 2.1005x; 2.1005x over previous
#include <cuda_runtime.h>
#include <cuda_fp16.h>

#define N_NODES 100000
#define N_EDGES 1600000
#define F 64
#define NTILES ((N_NODES + 1023) / 1024)   // 98
#define MTILES ((N_NODES + 63) / 64)       // 1563

typedef unsigned long long ull;

// ---------------- scratch (static device globals; no allocation) ----------------
__device__ int    g_deg[N_NODES];
__device__ int    g_cursor[N_NODES];
__device__ int    g_row_ptr[N_NODES + 1];
__device__ int    g_csr_src[N_EDGES];
__device__ int    g_tile_sum[NTILES];
__device__ int    g_tile_off[NTILES];
__device__ __half g_mh1[(size_t)N_NODES * 64];    // fp16 mean1 (layer-1 agg output)
__device__ __half g_cat2[(size_t)N_NODES * 128];  // [mean2 | h1] fp16, row 128
__device__ __half g_w1[64 * 128];                 // [W1l | W1r] fp16, row-major j,k
__device__ __half g_w2[64 * 128];
__device__ float  g_sa[N_NODES];
__device__ float  g_sb[N_NODES];

// ---------------- CSR build ----------------
__global__ void hist_kernel(const int* __restrict__ ei) {
    int e4 = blockIdx.x * blockDim.x + threadIdx.x;
    if (e4 >= N_EDGES / 4) return;
    int4 d = __ldg((const int4*)(ei + N_EDGES) + e4);
    atomicAdd(&g_deg[d.x], 1);
    atomicAdd(&g_deg[d.y], 1);
    atomicAdd(&g_deg[d.z], 1);
    atomicAdd(&g_deg[d.w], 1);
}

__global__ void scanA_kernel() {
    __shared__ int wsum[32];
    int t = threadIdx.x, b = blockIdx.x;
    int i = b * 1024 + t;
    int v = (i < N_NODES) ? g_deg[i] : 0;
#pragma unroll
    for (int off = 16; off; off >>= 1)
        v += __shfl_down_sync(0xFFFFFFFFu, v, off);
    if ((t & 31) == 0) wsum[t >> 5] = v;
    __syncthreads();
    if (t < 32) {
        int s = wsum[t];
#pragma unroll
        for (int off = 16; off; off >>= 1)
            s += __shfl_down_sync(0xFFFFFFFFu, s, off);
        if (t == 0) g_tile_sum[b] = s;
    }
}

__global__ void scanB_kernel() {
    __shared__ int sh[NTILES];
    int t = threadIdx.x;
    if (t < NTILES) sh[t] = g_tile_sum[t];
    __syncthreads();
    if (t == 0) {
        int run = 0;
        for (int i = 0; i < NTILES; i++) { int v = sh[i]; sh[i] = run; run += v; }
        g_row_ptr[N_NODES] = run;
    }
    __syncthreads();
    if (t < NTILES) g_tile_off[t] = sh[t];
}

__global__ void scanC_kernel() {
    __shared__ int wsum[32];
    int t = threadIdx.x, b = blockIdx.x;
    int i = b * 1024 + t;
    int v = (i < N_NODES) ? g_deg[i] : 0;
    int lane = t & 31, w = t >> 5;
    int x = v;
#pragma unroll
    for (int off = 1; off < 32; off <<= 1) {
        int y = __shfl_up_sync(0xFFFFFFFFu, x, off);
        if (lane >= off) x += y;
    }
    if (lane == 31) wsum[w] = x;
    __syncthreads();
    if (t < 32) {
        int s = wsum[t];
#pragma unroll
        for (int off = 1; off < 32; off <<= 1) {
            int y = __shfl_up_sync(0xFFFFFFFFu, s, off);
            if (t >= off) s += y;
        }
        wsum[t] = s;
    }
    __syncthreads();
    int base = g_tile_off[b] + (w ? wsum[w - 1] : 0);
    int excl = base + x - v;
    if (i < N_NODES) { g_row_ptr[i] = excl; g_cursor[i] = excl; }
}

__global__ void fill_kernel(const int* __restrict__ ei) {
    int e4 = blockIdx.x * blockDim.x + threadIdx.x;
    if (e4 >= N_EDGES / 4) return;
    int4 s = __ldg((const int4*)ei + e4);
    int4 d = __ldg((const int4*)(ei + N_EDGES) + e4);
    g_csr_src[atomicAdd(&g_cursor[d.x], 1)] = s.x;
    g_csr_src[atomicAdd(&g_cursor[d.y], 1)] = s.y;
    g_csr_src[atomicAdd(&g_cursor[d.z], 1)] = s.z;
    g_csr_src[atomicAdd(&g_cursor[d.w], 1)] = s.w;
}

// ---------------- weight prep: pack [Wl|Wr] into fp16 rows of 128 ----------------
__global__ void wprep_kernel(const float* __restrict__ W1l, const float* __restrict__ W1r,
                             const float* __restrict__ W2l, const float* __restrict__ W2r)
{
    int i = blockIdx.x * blockDim.x + threadIdx.x;   // 0..16383
    if (i >= 2 * 64 * 128) return;
    int sel = i >> 13;
    int r = i & 8191;
    int j = r >> 7, k = r & 127;
    const float* Wl = sel ? W2l : W1l;
    const float* Wr = sel ? W2r : W1r;
    float v = (k < 64) ? Wl[j * 64 + k] : Wr[j * 64 + (k - 64)];
    (sel ? g_w2 : g_w1)[r] = __float2half_rn(v);
}

// ---------------- agg layer 1: fp32 gather of x -> fp16 mean1 ----------------
__global__ void agg1_kernel(const float* __restrict__ xin) {
    int warp = (blockIdx.x * blockDim.x + threadIdx.x) >> 5;
    int lane = threadIdx.x & 31;
    if (warp >= N_NODES) return;

    const int beg = g_row_ptr[warp];
    const int end = g_row_ptr[warp + 1];
    const float2* __restrict__ x2 = (const float2*)xin;

    float2 a0 = make_float2(0.f, 0.f), a1 = make_float2(0.f, 0.f);
    float2 a2 = make_float2(0.f, 0.f), a3 = make_float2(0.f, 0.f);

    for (int base = beg; base < end; base += 8) {
        int s[8];
#pragma unroll
        for (int u = 0; u < 8; u++)
            s[u] = (base + u < end) ? __ldg(g_csr_src + base + u) : -1;
        float2 v[8];
#pragma unroll
        for (int u = 0; u < 8; u++)
            v[u] = (s[u] >= 0) ? __ldg(x2 + (size_t)s[u] * 32 + lane)
                               : make_float2(0.f, 0.f);
        a0.x += v[0].x + v[4].x; a0.y += v[0].y + v[4].y;
        a1.x += v[1].x + v[5].x; a1.y += v[1].y + v[5].y;
        a2.x += v[2].x + v[6].x; a2.y += v[2].y + v[6].y;
        a3.x += v[3].x + v[7].x; a3.y += v[3].y + v[7].y;
    }
    float2 acc;
    acc.x = (a0.x + a1.x) + (a2.x + a3.x);
    acc.y = (a0.y + a1.y) + (a2.y + a3.y);
    float inv = (end > beg) ? 1.0f / (float)(end - beg) : 0.0f;
    ((__half2*)g_mh1)[(size_t)warp * 32 + lane] = __floats2half2_rn(acc.x * inv, acc.y * inv);
}

// ---------------- agg layer 2: fp16 gather of h1 (cat2 right) -> fp16 mean2 (cat2 left) ----------------
__global__ void agg2_kernel() {
    int warp = (blockIdx.x * blockDim.x + threadIdx.x) >> 5;
    int lane = threadIdx.x & 31;
    if (warp >= N_NODES) return;

    const int beg = g_row_ptr[warp];
    const int end = g_row_ptr[warp + 1];
    const unsigned* __restrict__ xh = (const unsigned*)g_cat2;   // half2 units, row = 64

    float2 a0 = make_float2(0.f, 0.f), a1 = make_float2(0.f, 0.f);
    float2 a2 = make_float2(0.f, 0.f), a3 = make_float2(0.f, 0.f);

    for (int base = beg; base < end; base += 8) {
        int s[8];
#pragma unroll
        for (int u = 0; u < 8; u++)
            s[u] = (base + u < end) ? __ldg(g_csr_src + base + u) : -1;
        float2 v[8];
#pragma unroll
        for (int u = 0; u < 8; u++) {
            if (s[u] >= 0) {
                unsigned raw = __ldg(xh + (size_t)s[u] * 64 + 32 + lane);
                v[u] = __half22float2(*(__half2*)&raw);
            } else v[u] = make_float2(0.f, 0.f);
        }
        a0.x += v[0].x + v[4].x; a0.y += v[0].y + v[4].y;
        a1.x += v[1].x + v[5].x; a1.y += v[1].y + v[5].y;
        a2.x += v[2].x + v[6].x; a2.y += v[2].y + v[6].y;
        a3.x += v[3].x + v[7].x; a3.y += v[3].y + v[7].y;
    }
    float2 acc;
    acc.x = (a0.x + a1.x) + (a2.x + a3.x);
    acc.y = (a0.y + a1.y) + (a2.y + a3.y);
    float inv = (end > beg) ? 1.0f / (float)(end - beg) : 0.0f;
    ((__half2*)g_cat2)[(size_t)warp * 64 + lane] = __floats2half2_rn(acc.x * inv, acc.y * inv);
}

// ---------------- HMMA transform: out = relu([mean|x] @ [Wl|Wr]^T + b) ----------------
// 128 threads, 64-node tile per block. mma.sync.m16n8k16 f16->f32.
// LAYER 0: A = [mh1 | cvt(x fp32)], epilogue writes fp16 h1 into cat2 right half.
// LAYER 1: A = cat2 rows, epilogue reduces sa/sb per node (quad shfl, plain stores).
template<int LAYER>
__global__ void __launch_bounds__(128) gemm_kernel(
    const float* __restrict__ xsrc,
    const float* __restrict__ bias,
    const float* __restrict__ Wlin)
{
    __shared__ __half smA[64 * 136];   // 272B row stride: conflict-free quads
    const int m0 = blockIdx.x * 64;
    const int tid = threadIdx.x;
    const __half* __restrict__ W = (LAYER == 0) ? g_w1 : g_w2;

    if (LAYER == 0) {
        // left half: fp16 mean1 rows (128B each) = 512 16B chunks
#pragma unroll
        for (int i = 0; i < 4; i++) {
            int chunk = tid + i * 128;
            int r = chunk >> 3, c = chunk & 7;
            uint4 v = make_uint4(0, 0, 0, 0);
            if (m0 + r < N_NODES) v = *(const uint4*)(g_mh1 + (size_t)(m0 + r) * 64 + c * 8);
            *(uint4*)(smA + r * 136 + c * 8) = v;
        }
        // right half: fp32 x -> fp16, 64 rows x 16 float4 chunks
#pragma unroll
        for (int i = 0; i < 8; i++) {
            int chunk = tid + i * 128;
            int r = chunk >> 4, c = chunk & 15;
            float4 v = make_float4(0.f, 0.f, 0.f, 0.f);
            if (m0 + r < N_NODES) v = __ldg((const float4*)(xsrc + (size_t)(m0 + r) * 64) + c);
            *(__half2*)(smA + r * 136 + 64 + c * 4)     = __floats2half2_rn(v.x, v.y);
            *(__half2*)(smA + r * 136 + 64 + c * 4 + 2) = __floats2half2_rn(v.z, v.w);
        }
    } else {
#pragma unroll
        for (int i = 0; i < 8; i++) {
            int chunk = tid + i * 128;
            int r = chunk >> 4, c = chunk & 15;
            uint4 v = make_uint4(0, 0, 0, 0);
            if (m0 + r < N_NODES) v = *(const uint4*)(g_cat2 + (size_t)(m0 + r) * 128 + c * 8);
            *(uint4*)(smA + r * 136 + c * 8) = v;
        }
    }
    __syncthreads();

    const int w = tid >> 5, lane = tid & 31;
    const int qr = lane >> 2, qc = lane & 3;
    const int r0 = w * 16;

    // A fragments (held for all N-tiles): a[k] = 16x16 tile at k*16
    unsigned a[8][4];
#pragma unroll
    for (int k = 0; k < 8; k++) {
        const __half* base = smA + (r0 + qr) * 136 + k * 16 + qc * 2;
        a[k][0] = *(const unsigned*)(base);
        a[k][1] = *(const unsigned*)(base + 8 * 136);
        a[k][2] = *(const unsigned*)(base + 8);
        a[k][3] = *(const unsigned*)(base + 8 * 136 + 8);
    }

    float pa0 = 0.f, pb0 = 0.f, pa1 = 0.f, pb1 = 0.f;

#pragma unroll
    for (int nt = 0; nt < 8; nt++) {
        const int j0 = nt * 8;
        float c0 = 0.f, c1 = 0.f, c2 = 0.f, c3 = 0.f;
#pragma unroll
        for (int k = 0; k < 8; k++) {
            const __half* bb = W + (size_t)(j0 + qr) * 128 + k * 16 + qc * 2;
            unsigned b0 = __ldg((const unsigned*)bb);
            unsigned b1 = __ldg((const unsigned*)(bb + 8));
            asm volatile(
                "mma.sync.aligned.m16n8k16.row.col.f32.f16.f16.f32 "
                "{%0,%1,%2,%3}, {%4,%5,%6,%7}, {%8,%9}, {%0,%1,%2,%3};"
                : "+f"(c0), "+f"(c1), "+f"(c2), "+f"(c3)
                : "r"(a[k][0]), "r"(a[k][1]), "r"(a[k][2]), "r"(a[k][3]),
                  "r"(b0), "r"(b1));
        }
        float2 bj = *(const float2*)(bias + j0 + qc * 2);
        float h0 = fmaxf(c0 + bj.x, 0.f);
        float h1 = fmaxf(c1 + bj.y, 0.f);
        float h2 = fmaxf(c2 + bj.x, 0.f);
        float h3 = fmaxf(c3 + bj.y, 0.f);

        if (LAYER == 0) {
            int g0 = m0 + r0 + qr, g1 = g0 + 8;
            if (g0 < N_NODES)
                *(__half2*)(g_cat2 + (size_t)g0 * 128 + 64 + j0 + qc * 2) = __floats2half2_rn(h0, h1);
            if (g1 < N_NODES)
                *(__half2*)(g_cat2 + (size_t)g1 * 128 + 64 + j0 + qc * 2) = __floats2half2_rn(h2, h3);
        } else {
            float2 wa = *(const float2*)(Wlin + j0 + qc * 2);
            float2 wb = *(const float2*)(Wlin + 64 + j0 + qc * 2);
            pa0 += h0 * wa.x + h1 * wa.y;  pb0 += h0 * wb.x + h1 * wb.y;
            pa1 += h2 * wa.x + h3 * wa.y;  pb1 += h2 * wb.x + h3 * wb.y;
        }
    }

    if (LAYER == 1) {
        // quad reduction (lanes sharing a row), then plain stores — no atomics.
        pa0 += __shfl_xor_sync(0xFFFFFFFFu, pa0, 1); pa0 += __shfl_xor_sync(0xFFFFFFFFu, pa0, 2);
        pb0 += __shfl_xor_sync(0xFFFFFFFFu, pb0, 1); pb0 += __shfl_xor_sync(0xFFFFFFFFu, pb0, 2);
        pa1 += __shfl_xor_sync(0xFFFFFFFFu, pa1, 1); pa1 += __shfl_xor_sync(0xFFFFFFFFu, pa1, 2);
        pb1 += __shfl_xor_sync(0xFFFFFFFFu, pb1, 1); pb1 += __shfl_xor_sync(0xFFFFFFFFu, pb1, 2);
        if (qc == 0) {
            int g0 = m0 + r0 + qr, g1 = g0 + 8;
            if (g0 < N_NODES) { g_sa[g0] = pa0; g_sb[g0] = pb0; }
            if (g1 < N_NODES) { g_sa[g1] = pa1; g_sb[g1] = pb1; }
        }
    }
}

// ---------------- final edge scores (4 edges per thread) ----------------
__global__ void edge_kernel(const int* __restrict__ ei,
                            const float* __restrict__ blin,
                            float* __restrict__ out)
{
    int e4 = blockIdx.x * blockDim.x + threadIdx.x;
    if (e4 >= N_EDGES / 4) return;
    int4 s = __ldg((const int4*)ei + e4);
    int4 d = __ldg((const int4*)(ei + N_EDGES) + e4);
    float b = __ldg(blin);
    float4 r;
    r.x = g_sa[s.x] + g_sb[d.x] + b;
    r.y = g_sa[s.y] + g_sb[d.y] + b;
    r.z = g_sa[s.z] + g_sb[d.z] + b;
    r.w = g_sa[s.w] + g_sb[d.w] + b;
    ((float4*)out)[e4] = r;
}

// ---------------- launch ----------------
extern "C" void kernel_launch(void* const* d_in, const int* in_sizes, int n_in,
                              void* d_out, int out_size)
{
    const float* x    = (const float*)d_in[0];
    const int*   ei   = (const int*)  d_in[1];
    const float* W1l  = (const float*)d_in[2];
    const float* b1l  = (const float*)d_in[3];
    const float* W1r  = (const float*)d_in[4];
    const float* W2l  = (const float*)d_in[5];
    const float* b2l  = (const float*)d_in[6];
    const float* W2r  = (const float*)d_in[7];
    const float* Wlin = (const float*)d_in[8];
    const float* blin = (const float*)d_in[9];
    float* out = (float*)d_out;

    const int E4B = (N_EDGES / 4 + 255) / 256;

    int* p_deg; cudaGetSymbolAddress((void**)&p_deg, g_deg);
    cudaMemsetAsync(p_deg, 0, N_NODES * sizeof(int), 0);   // memset node, not a kernel

    hist_kernel<<<E4B, 256>>>(ei);
    scanA_kernel<<<NTILES, 1024>>>();
    scanB_kernel<<<1, 128>>>();
    scanC_kernel<<<NTILES, 1024>>>();
    fill_kernel<<<E4B, 256>>>(ei);

    // layer 1
    agg1_kernel<<<N_NODES * 32 / 256, 256>>>(x);
    wprep_kernel<<<(2 * 64 * 128 + 255) / 256, 256>>>(W1l, W1r, W2l, W2r);
    gemm_kernel<0><<<MTILES, 128>>>(x, b1l, nullptr);

    // layer 2 (h2 never materialized; sa/sb produced in epilogue)
    agg2_kernel<<<N_NODES * 32 / 256, 256>>>();
    gemm_kernel<1><<<MTILES, 128>>>(nullptr, b2l, Wlin);

    // edge scoring
    edge_kernel<<<E4B, 256>>>(ei, blin, out);
}